// round 1
// baseline (speedup 1.0000x reference)
#include <cuda_runtime.h>

// Problem constants (fixed by the dataset)
#define BATCH 2
#define SEQ   2048
#define DMODEL 1024
#define NHEAD 16
#define HDIM  64
#define MROWS (BATCH*SEQ)   // 4096
#define BHCNT (BATCH*NHEAD) // 32

// Scratch (allocation-free rule: __device__ globals). 4 x 16 MB.
__device__ float g_q[MROWS*DMODEL];
__device__ float g_k[MROWS*DMODEL];
__device__ float g_v[MROWS*DMODEL];
__device__ float g_att[MROWS*DMODEL];

// ---------------------------------------------------------------------------
// SGEMM: C[M,N] = A[M,K] @ W[N,K]^T (+ bias[n])   (nn.Linear semantics)
// BM=BN=128, BK=8, 256 threads, 8x8 per thread.
// ---------------------------------------------------------------------------
template<bool HAS_BIAS>
__device__ __forceinline__ void sgemm_body(const float* __restrict__ A,
                                           const float* __restrict__ W,
                                           const float* __restrict__ bias,
                                           float* __restrict__ C,
                                           int N, int K)
{
    constexpr int BM = 128, BN = 128, BK = 8, TM = 8, TN = 8;
    __shared__ float As[BK][BM];
    __shared__ float Bs[BK][BN];

    const int tid = threadIdx.x;
    const int ty = tid >> 4;      // 0..15 -> row block
    const int tx = tid & 15;      // 0..15 -> col block

    const int rowTile = blockIdx.y * BM;
    const int colTile = blockIdx.x * BN;

    const float* Ap = A + (size_t)rowTile * K;
    const float* Wp = W + (size_t)colTile * K;

    const int loadRow = tid >> 1;        // 0..127
    const int loadCol = (tid & 1) << 2;  // 0 or 4

    float acc[TM][TN];
#pragma unroll
    for (int i = 0; i < TM; i++)
#pragma unroll
        for (int j = 0; j < TN; j++) acc[i][j] = 0.f;

    for (int k0 = 0; k0 < K; k0 += BK) {
        float4 a4 = *(const float4*)(Ap + (size_t)loadRow * K + k0 + loadCol);
        As[loadCol + 0][loadRow] = a4.x;
        As[loadCol + 1][loadRow] = a4.y;
        As[loadCol + 2][loadRow] = a4.z;
        As[loadCol + 3][loadRow] = a4.w;
        float4 b4 = *(const float4*)(Wp + (size_t)loadRow * K + k0 + loadCol);
        Bs[loadCol + 0][loadRow] = b4.x;
        Bs[loadCol + 1][loadRow] = b4.y;
        Bs[loadCol + 2][loadRow] = b4.z;
        Bs[loadCol + 3][loadRow] = b4.w;
        __syncthreads();

#pragma unroll
        for (int kk = 0; kk < BK; kk++) {
            float ar[TM], br[TN];
            *(float4*)&ar[0] = *(const float4*)&As[kk][ty * TM];
            *(float4*)&ar[4] = *(const float4*)&As[kk][ty * TM + 4];
            *(float4*)&br[0] = *(const float4*)&Bs[kk][tx * TN];
            *(float4*)&br[4] = *(const float4*)&Bs[kk][tx * TN + 4];
#pragma unroll
            for (int i = 0; i < TM; i++)
#pragma unroll
                for (int j = 0; j < TN; j++)
                    acc[i][j] += ar[i] * br[j];
        }
        __syncthreads();
    }

#pragma unroll
    for (int i = 0; i < TM; i++) {
        const int row = rowTile + ty * TM + i;
#pragma unroll
        for (int j = 0; j < TN; j += 4) {
            const int col = colTile + tx * TN + j;
            float4 v = make_float4(acc[i][j], acc[i][j + 1], acc[i][j + 2], acc[i][j + 3]);
            if (HAS_BIAS) {
                v.x += bias[col + 0];
                v.y += bias[col + 1];
                v.z += bias[col + 2];
                v.w += bias[col + 3];
            }
            *(float4*)(C + (size_t)row * N + col) = v;
        }
    }
}

__global__ void qkv_kernel(const float* __restrict__ X,
                           const float* __restrict__ Wq,
                           const float* __restrict__ Wk,
                           const float* __restrict__ Wv)
{
    const float* Wm;
    float* C;
    if (blockIdx.z == 0)      { Wm = Wq; C = g_q; }
    else if (blockIdx.z == 1) { Wm = Wk; C = g_k; }
    else                      { Wm = Wv; C = g_v; }
    sgemm_body<false>(X, Wm, nullptr, C, DMODEL, DMODEL);
}

__global__ void out_kernel(const float* __restrict__ Wo,
                           const float* __restrict__ bo,
                           float* __restrict__ out)
{
    sgemm_body<true>(g_att, Wo, bo, out, DMODEL, DMODEL);
}

// ---------------------------------------------------------------------------
// Causal flash attention, fp32, NO 1/sqrt(hd) scaling (matches reference).
// Layout: g_q/g_k/g_v are (BH, L, 64) contiguous per head-batch (this is
// exactly the buggy-reshape layout of the reference).
// Block: 256 threads; one (bh, 64-query tile) per block; kv tiles of 64.
// Thread (tr= t/16, tc = t%15..): 4x4 register tile of the 64x64 S / O tiles.
// ---------------------------------------------------------------------------
#define QS_STRIDE 65
__global__ void attn_kernel()
{
    extern __shared__ float sh[];
    float* Qs = sh;                         // [64][65]
    float* Ks = Qs + 64 * QS_STRIDE;        // [64][65]
    float* Vs = Ks + 64 * QS_STRIDE;        // [64][64]
    float* Ps = Vs + 64 * 64;               // [64][64]

    const int bh = blockIdx.y;   // 0..31
    const int qi = blockIdx.x;   // 0..31  (query tile)
    const size_t base = (size_t)bh * SEQ * HDIM;
    const float* Qp = g_q + base + (size_t)qi * 64 * HDIM;
    const float* Kp = g_k + base;
    const float* Vp = g_v + base;
    float* Op = g_att + base + (size_t)qi * 64 * HDIM;

    const int t = threadIdx.x;
    const int tr = t >> 4;   // 0..15 : rows tr*4..tr*4+3
    const int tc = t & 15;   // 0..15 : cols tc*4..tc*4+3

    // Load Q tile (64x64) into padded smem
    for (int i = t; i < 64 * 16; i += 256) {
        const int row = i >> 4;
        const int c4 = (i & 15) << 2;
        float4 v = *(const float4*)(Qp + row * HDIM + c4);
        Qs[row * QS_STRIDE + c4 + 0] = v.x;
        Qs[row * QS_STRIDE + c4 + 1] = v.y;
        Qs[row * QS_STRIDE + c4 + 2] = v.z;
        Qs[row * QS_STRIDE + c4 + 3] = v.w;
    }

    float m[4], lsum[4], o[4][4];
#pragma unroll
    for (int i = 0; i < 4; i++) {
        m[i] = -1e30f; lsum[i] = 0.f;
#pragma unroll
        for (int j = 0; j < 4; j++) o[i][j] = 0.f;
    }

    for (int j = 0; j <= qi; j++) {
        __syncthreads();  // protect Q load (first iter) / prior Ps,Ks,Vs reads
        const float* Kt = Kp + (size_t)j * 64 * HDIM;
        const float* Vt = Vp + (size_t)j * 64 * HDIM;
        for (int i = t; i < 64 * 16; i += 256) {
            const int row = i >> 4;
            const int c4 = (i & 15) << 2;
            float4 kv = *(const float4*)(Kt + row * HDIM + c4);
            Ks[row * QS_STRIDE + c4 + 0] = kv.x;
            Ks[row * QS_STRIDE + c4 + 1] = kv.y;
            Ks[row * QS_STRIDE + c4 + 2] = kv.z;
            Ks[row * QS_STRIDE + c4 + 3] = kv.w;
            *(float4*)&Vs[row * 64 + c4] = *(const float4*)(Vt + row * HDIM + c4);
        }
        __syncthreads();

        // S = Q @ K^T (64x64 tile), 4x4 per thread
        float s[4][4];
#pragma unroll
        for (int ii = 0; ii < 4; ii++)
#pragma unroll
            for (int jj = 0; jj < 4; jj++) s[ii][jj] = 0.f;

#pragma unroll 8
        for (int k = 0; k < HDIM; k++) {
            float a0 = Qs[(tr * 4 + 0) * QS_STRIDE + k];
            float a1 = Qs[(tr * 4 + 1) * QS_STRIDE + k];
            float a2 = Qs[(tr * 4 + 2) * QS_STRIDE + k];
            float a3 = Qs[(tr * 4 + 3) * QS_STRIDE + k];
            float b0 = Ks[(tc * 4 + 0) * QS_STRIDE + k];
            float b1 = Ks[(tc * 4 + 1) * QS_STRIDE + k];
            float b2 = Ks[(tc * 4 + 2) * QS_STRIDE + k];
            float b3 = Ks[(tc * 4 + 3) * QS_STRIDE + k];
            s[0][0] += a0 * b0; s[0][1] += a0 * b1; s[0][2] += a0 * b2; s[0][3] += a0 * b3;
            s[1][0] += a1 * b0; s[1][1] += a1 * b1; s[1][2] += a1 * b2; s[1][3] += a1 * b3;
            s[2][0] += a2 * b0; s[2][1] += a2 * b1; s[2][2] += a2 * b2; s[2][3] += a2 * b3;
            s[3][0] += a3 * b0; s[3][1] += a3 * b1; s[3][2] += a3 * b2; s[3][3] += a3 * b3;
        }

        // Causal mask on the diagonal tile
        if (j == qi) {
#pragma unroll
            for (int ii = 0; ii < 4; ii++)
#pragma unroll
                for (int jj = 0; jj < 4; jj++)
                    if (tc * 4 + jj > tr * 4 + ii) s[ii][jj] = -1e30f;
        }

        // Online softmax update (row reduce across 16 lanes sharing tr)
#pragma unroll
        for (int ii = 0; ii < 4; ii++) {
            float rowmax = fmaxf(fmaxf(s[ii][0], s[ii][1]), fmaxf(s[ii][2], s[ii][3]));
#pragma unroll
            for (int off = 1; off < 16; off <<= 1)
                rowmax = fmaxf(rowmax, __shfl_xor_sync(0xffffffffu, rowmax, off));
            const float mnew = fmaxf(m[ii], rowmax);
            const float scale = __expf(m[ii] - mnew);
            m[ii] = mnew;
            float p0 = __expf(s[ii][0] - mnew);
            float p1 = __expf(s[ii][1] - mnew);
            float p2 = __expf(s[ii][2] - mnew);
            float p3 = __expf(s[ii][3] - mnew);
            s[ii][0] = p0; s[ii][1] = p1; s[ii][2] = p2; s[ii][3] = p3;
            float rs = (p0 + p1) + (p2 + p3);
#pragma unroll
            for (int off = 1; off < 16; off <<= 1)
                rs += __shfl_xor_sync(0xffffffffu, rs, off);
            lsum[ii] = lsum[ii] * scale + rs;
            o[ii][0] *= scale; o[ii][1] *= scale; o[ii][2] *= scale; o[ii][3] *= scale;
        }

        // Stage P through shared for the PV GEMM
#pragma unroll
        for (int ii = 0; ii < 4; ii++)
            *(float4*)&Ps[(tr * 4 + ii) * 64 + tc * 4] =
                make_float4(s[ii][0], s[ii][1], s[ii][2], s[ii][3]);
        __syncthreads();

        // O += P @ V (64x64 tile), 4x4 per thread
#pragma unroll 8
        for (int k = 0; k < 64; k++) {
            float a0 = Ps[(tr * 4 + 0) * 64 + k];
            float a1 = Ps[(tr * 4 + 1) * 64 + k];
            float a2 = Ps[(tr * 4 + 2) * 64 + k];
            float a3 = Ps[(tr * 4 + 3) * 64 + k];
            float4 b = *(const float4*)&Vs[k * 64 + tc * 4];
            o[0][0] += a0 * b.x; o[0][1] += a0 * b.y; o[0][2] += a0 * b.z; o[0][3] += a0 * b.w;
            o[1][0] += a1 * b.x; o[1][1] += a1 * b.y; o[1][2] += a1 * b.z; o[1][3] += a1 * b.w;
            o[2][0] += a2 * b.x; o[2][1] += a2 * b.y; o[2][2] += a2 * b.z; o[2][3] += a2 * b.w;
            o[3][0] += a3 * b.x; o[3][1] += a3 * b.y; o[3][2] += a3 * b.z; o[3][3] += a3 * b.w;
        }
    }

    // Normalize and write O tile
#pragma unroll
    for (int ii = 0; ii < 4; ii++) {
        const float inv = 1.f / lsum[ii];
        const int row = tr * 4 + ii;
        float4 v = make_float4(o[ii][0] * inv, o[ii][1] * inv, o[ii][2] * inv, o[ii][3] * inv);
        *(float4*)(Op + row * HDIM + tc * 4) = v;
    }
}

// ---------------------------------------------------------------------------
extern "C" void kernel_launch(void* const* d_in, const int* in_sizes, int n_in,
                              void* d_out, int out_size)
{
    const float* X  = (const float*)d_in[0];
    const float* Wq = (const float*)d_in[1];
    const float* Wk = (const float*)d_in[2];
    const float* Wv = (const float*)d_in[3];
    const float* Wo = (const float*)d_in[4];
    const float* bo = (const float*)d_in[5];
    float* out = (float*)d_out;

    const int attn_smem = (2 * 64 * QS_STRIDE + 2 * 64 * 64) * (int)sizeof(float); // 66048
    cudaFuncSetAttribute(attn_kernel, cudaFuncAttributeMaxDynamicSharedMemorySize, attn_smem);

    // Q,K,V projections: C = X @ W^T  (M=4096, N=K=1024)
    qkv_kernel<<<dim3(DMODEL / 128, MROWS / 128, 3), 256>>>(X, Wq, Wk, Wv);
    // Causal attention per (bh, qtile)
    attn_kernel<<<dim3(SEQ / 64, BHCNT), 256, attn_smem>>>();
    // Output projection + bias
    out_kernel<<<dim3(DMODEL / 128, MROWS / 128), 256>>>(Wo, bo, out);
}

// round 4
// speedup vs baseline: 1.1270x; 1.1270x over previous
#include <cuda_runtime.h>
#include <cstdint>

// Problem constants
#define SEQ    2048
#define DMODEL 1024
#define NHEAD  16
#define HDIM   64
#define MROWS  4096   // B*L
#define BHCNT  32     // B*H

// Scratch (__device__ globals: allocation-free rule)
__device__ float g_q[MROWS * DMODEL];
__device__ float g_k[MROWS * DMODEL];
__device__ float g_v[MROWS * DMODEL];
__device__ float g_att[MROWS * DMODEL];

// ---------------------------------------------------------------------------
// Helpers (baseline sm_100-safe: mma.sync + cp.async only)
// ---------------------------------------------------------------------------
__device__ __forceinline__ void cp_async16(uint32_t s, const void* g) {
    asm volatile("cp.async.cg.shared.global [%0], [%1], 16;" ::"r"(s), "l"(g) : "memory");
}
__device__ __forceinline__ uint32_t smem_u32(const void* p) {
    uint32_t a;
    asm("{ .reg .u64 t; cvta.to.shared.u64 t, %1; cvt.u32.u64 %0, t; }" : "=r"(a) : "l"(p));
    return a;
}
__device__ __forceinline__ uint32_t f2tf32(float f) {
    uint32_t u;
    asm("cvt.rna.tf32.f32 %0, %1;" : "=r"(u) : "f"(f));
    return u;
}
// 3xTF32 split: f = hi + lo (+ O(2^-22))
__device__ __forceinline__ void split_tf32(float f, uint32_t& hi, uint32_t& lo) {
    hi = f2tf32(f);
    lo = f2tf32(f - __uint_as_float(hi));
}
__device__ __forceinline__ void mma_tf32(float* c, const uint32_t* a, const uint32_t* b) {
    asm volatile(
        "mma.sync.aligned.m16n8k8.row.col.f32.tf32.tf32.f32 "
        "{%0,%1,%2,%3}, {%4,%5,%6,%7}, {%8,%9}, {%0,%1,%2,%3};"
        : "+f"(c[0]), "+f"(c[1]), "+f"(c[2]), "+f"(c[3])
        : "r"(a[0]), "r"(a[1]), "r"(a[2]), "r"(a[3]), "r"(b[0]), "r"(b[1]));
}

// Swizzled smem index for a [rows][32-float] tile: 16B-chunk XOR swizzle.
__device__ __forceinline__ int sidx(int r, int k) {
    return r * 32 + ((((k >> 2) ^ (r & 7)) << 2) | (k & 3));
}

// ---------------------------------------------------------------------------
// 3xTF32 mma.sync GEMM: C[M,N] = A[M,K] @ W[N,K]^T (+bias), M=4096, N=K=1024.
// CTA tile 128x128, BK=32, 256 threads (8 warps = 2m x 4n), warp tile 64x32.
// Double-buffered cp.async.
// ---------------------------------------------------------------------------
#define GBM 128
#define GBN 128
#define GBK 32
#define GNKT (DMODEL / GBK)                    // 32
#define STG_FLOATS ((GBM + GBN) * GBK)         // 8192 floats = 32KB
#define GSMEM (2 * STG_FLOATS * 4)             // 64KB

template<bool HAS_BIAS>
__device__ __forceinline__ void gemm_mma_body(const float* __restrict__ A,
                                              const float* __restrict__ W,
                                              const float* __restrict__ bias,
                                              float* __restrict__ C)
{
    extern __shared__ float sm[];
    const int tid = threadIdx.x;
    const int wid = tid >> 5;
    const int lane = tid & 31;
    const int gr = lane >> 2;   // groupID (0..7)
    const int tg = lane & 3;    // threadID_in_group (0..3)
    const int m0 = blockIdx.y * GBM;
    const int n0 = blockIdx.x * GBN;
    const int wm = (wid >> 2) * 64;   // warp m offset in tile
    const int wn = (wid & 3) * 32;    // warp n offset in tile

    float* As[2] = { sm, sm + STG_FLOATS };
    float* Bs[2] = { sm + GBM * GBK, sm + STG_FLOATS + GBM * GBK };

    float acc[4][4][4];
#pragma unroll
    for (int i = 0; i < 4; i++)
#pragma unroll
        for (int j = 0; j < 4; j++)
#pragma unroll
            for (int c = 0; c < 4; c++) acc[i][j][c] = 0.f;

    auto load_tile = [&](int stg, int k0) {
        float* as = As[stg];
        float* bs = Bs[stg];
#pragma unroll
        for (int i = 0; i < 4; i++) {
            const int ch = tid + i * 256;
            const int row = ch >> 3, c = ch & 7;
            cp_async16(smem_u32(as + row * 32 + (((c ^ (row & 7)) << 2))),
                       A + (size_t)(m0 + row) * DMODEL + k0 + c * 4);
        }
#pragma unroll
        for (int i = 0; i < 4; i++) {
            const int ch = tid + i * 256;
            const int row = ch >> 3, c = ch & 7;
            cp_async16(smem_u32(bs + row * 32 + (((c ^ (row & 7)) << 2))),
                       W + (size_t)(n0 + row) * DMODEL + k0 + c * 4);
        }
    };

    load_tile(0, 0);
    asm volatile("cp.async.commit_group;" ::: "memory");

    for (int kt = 0; kt < GNKT; kt++) {
        if (kt + 1 < GNKT) load_tile((kt + 1) & 1, (kt + 1) * GBK);
        asm volatile("cp.async.commit_group;" ::: "memory");
        asm volatile("cp.async.wait_group 1;" ::: "memory");
        __syncthreads();

        const float* as = As[kt & 1];
        const float* bs = Bs[kt & 1];
#pragma unroll
        for (int ks = 0; ks < 4; ks++) {
            const int k = ks * 8 + tg;
            uint32_t ah[4][4], al[4][4];
#pragma unroll
            for (int mi = 0; mi < 4; mi++) {
                const int m = wm + mi * 16 + gr;
                split_tf32(as[sidx(m,     k)],     ah[mi][0], al[mi][0]);
                split_tf32(as[sidx(m + 8, k)],     ah[mi][1], al[mi][1]);
                split_tf32(as[sidx(m,     k + 4)], ah[mi][2], al[mi][2]);
                split_tf32(as[sidx(m + 8, k + 4)], ah[mi][3], al[mi][3]);
            }
#pragma unroll
            for (int nj = 0; nj < 4; nj++) {
                const int n = wn + nj * 8 + gr;
                uint32_t bh[2], bl[2];
                split_tf32(bs[sidx(n, k)],     bh[0], bl[0]);
                split_tf32(bs[sidx(n, k + 4)], bh[1], bl[1]);
#pragma unroll
                for (int mi = 0; mi < 4; mi++) {
                    mma_tf32(acc[mi][nj], al[mi], bh);   // lo*hi
                    mma_tf32(acc[mi][nj], ah[mi], bl);   // hi*lo
                    mma_tf32(acc[mi][nj], ah[mi], bh);   // hi*hi
                }
            }
        }
        __syncthreads();
    }

    // Epilogue: fragment -> global (float2 stores)
#pragma unroll
    for (int mi = 0; mi < 4; mi++) {
        const int row = m0 + wm + mi * 16 + gr;
#pragma unroll
        for (int nj = 0; nj < 4; nj++) {
            const int col = n0 + wn + nj * 8 + 2 * tg;
            float2 v0 = make_float2(acc[mi][nj][0], acc[mi][nj][1]);
            float2 v1 = make_float2(acc[mi][nj][2], acc[mi][nj][3]);
            if (HAS_BIAS) {
                const float b0 = bias[col], b1 = bias[col + 1];
                v0.x += b0; v0.y += b1; v1.x += b0; v1.y += b1;
            }
            *(float2*)(C + (size_t)row * DMODEL + col) = v0;
            *(float2*)(C + (size_t)(row + 8) * DMODEL + col) = v1;
        }
    }
}

__global__ void __launch_bounds__(256) qkv_mma_kernel(const float* __restrict__ X,
                                                      const float* __restrict__ Wq,
                                                      const float* __restrict__ Wk,
                                                      const float* __restrict__ Wv)
{
    const float* Wm;
    float* C;
    if (blockIdx.z == 0)      { Wm = Wq; C = g_q; }
    else if (blockIdx.z == 1) { Wm = Wk; C = g_k; }
    else                      { Wm = Wv; C = g_v; }
    gemm_mma_body<false>(X, Wm, nullptr, C);
}

__global__ void __launch_bounds__(256) out_mma_kernel(const float* __restrict__ Wo,
                                                      const float* __restrict__ bo,
                                                      float* __restrict__ out)
{
    gemm_mma_body<true>(g_att, Wo, bo, out);
}

// ---------------------------------------------------------------------------
// Causal flash attention, fp32, no scaling (proven R1 version; R5 target).
// ---------------------------------------------------------------------------
#define QS_STRIDE 65
__global__ void attn_kernel()
{
    extern __shared__ float sh[];
    float* Qs = sh;
    float* Ks = Qs + 64 * QS_STRIDE;
    float* Vs = Ks + 64 * QS_STRIDE;
    float* Ps = Vs + 64 * 64;

    const int bh = blockIdx.y;
    const int qi = blockIdx.x;
    const size_t base = (size_t)bh * SEQ * HDIM;
    const float* Qp = g_q + base + (size_t)qi * 64 * HDIM;
    const float* Kp = g_k + base;
    const float* Vp = g_v + base;
    float* Op = g_att + base + (size_t)qi * 64 * HDIM;

    const int t = threadIdx.x;
    const int tr = t >> 4;
    const int tc = t & 15;

    for (int i = t; i < 64 * 16; i += 256) {
        const int row = i >> 4;
        const int c4 = (i & 15) << 2;
        float4 v = *(const float4*)(Qp + row * HDIM + c4);
        Qs[row * QS_STRIDE + c4 + 0] = v.x;
        Qs[row * QS_STRIDE + c4 + 1] = v.y;
        Qs[row * QS_STRIDE + c4 + 2] = v.z;
        Qs[row * QS_STRIDE + c4 + 3] = v.w;
    }

    float m[4], lsum[4], o[4][4];
#pragma unroll
    for (int i = 0; i < 4; i++) {
        m[i] = -1e30f; lsum[i] = 0.f;
#pragma unroll
        for (int j = 0; j < 4; j++) o[i][j] = 0.f;
    }

    for (int j = 0; j <= qi; j++) {
        __syncthreads();
        const float* Kt = Kp + (size_t)j * 64 * HDIM;
        const float* Vt = Vp + (size_t)j * 64 * HDIM;
        for (int i = t; i < 64 * 16; i += 256) {
            const int row = i >> 4;
            const int c4 = (i & 15) << 2;
            float4 kv = *(const float4*)(Kt + row * HDIM + c4);
            Ks[row * QS_STRIDE + c4 + 0] = kv.x;
            Ks[row * QS_STRIDE + c4 + 1] = kv.y;
            Ks[row * QS_STRIDE + c4 + 2] = kv.z;
            Ks[row * QS_STRIDE + c4 + 3] = kv.w;
            *(float4*)&Vs[row * 64 + c4] = *(const float4*)(Vt + row * HDIM + c4);
        }
        __syncthreads();

        float s[4][4];
#pragma unroll
        for (int ii = 0; ii < 4; ii++)
#pragma unroll
            for (int jj = 0; jj < 4; jj++) s[ii][jj] = 0.f;

#pragma unroll 8
        for (int k = 0; k < HDIM; k++) {
            float a0 = Qs[(tr * 4 + 0) * QS_STRIDE + k];
            float a1 = Qs[(tr * 4 + 1) * QS_STRIDE + k];
            float a2 = Qs[(tr * 4 + 2) * QS_STRIDE + k];
            float a3 = Qs[(tr * 4 + 3) * QS_STRIDE + k];
            float b0 = Ks[(tc * 4 + 0) * QS_STRIDE + k];
            float b1 = Ks[(tc * 4 + 1) * QS_STRIDE + k];
            float b2 = Ks[(tc * 4 + 2) * QS_STRIDE + k];
            float b3 = Ks[(tc * 4 + 3) * QS_STRIDE + k];
            s[0][0] += a0 * b0; s[0][1] += a0 * b1; s[0][2] += a0 * b2; s[0][3] += a0 * b3;
            s[1][0] += a1 * b0; s[1][1] += a1 * b1; s[1][2] += a1 * b2; s[1][3] += a1 * b3;
            s[2][0] += a2 * b0; s[2][1] += a2 * b1; s[2][2] += a2 * b2; s[2][3] += a2 * b3;
            s[3][0] += a3 * b0; s[3][1] += a3 * b1; s[3][2] += a3 * b2; s[3][3] += a3 * b3;
        }

        if (j == qi) {
#pragma unroll
            for (int ii = 0; ii < 4; ii++)
#pragma unroll
                for (int jj = 0; jj < 4; jj++)
                    if (tc * 4 + jj > tr * 4 + ii) s[ii][jj] = -1e30f;
        }

#pragma unroll
        for (int ii = 0; ii < 4; ii++) {
            float rowmax = fmaxf(fmaxf(s[ii][0], s[ii][1]), fmaxf(s[ii][2], s[ii][3]));
#pragma unroll
            for (int off = 1; off < 16; off <<= 1)
                rowmax = fmaxf(rowmax, __shfl_xor_sync(0xffffffffu, rowmax, off));
            const float mnew = fmaxf(m[ii], rowmax);
            const float scale = __expf(m[ii] - mnew);
            m[ii] = mnew;
            float p0 = __expf(s[ii][0] - mnew);
            float p1 = __expf(s[ii][1] - mnew);
            float p2 = __expf(s[ii][2] - mnew);
            float p3 = __expf(s[ii][3] - mnew);
            s[ii][0] = p0; s[ii][1] = p1; s[ii][2] = p2; s[ii][3] = p3;
            float rs = (p0 + p1) + (p2 + p3);
#pragma unroll
            for (int off = 1; off < 16; off <<= 1)
                rs += __shfl_xor_sync(0xffffffffu, rs, off);
            lsum[ii] = lsum[ii] * scale + rs;
            o[ii][0] *= scale; o[ii][1] *= scale; o[ii][2] *= scale; o[ii][3] *= scale;
        }

#pragma unroll
        for (int ii = 0; ii < 4; ii++)
            *(float4*)&Ps[(tr * 4 + ii) * 64 + tc * 4] =
                make_float4(s[ii][0], s[ii][1], s[ii][2], s[ii][3]);
        __syncthreads();

#pragma unroll 8
        for (int k = 0; k < 64; k++) {
            float a0 = Ps[(tr * 4 + 0) * 64 + k];
            float a1 = Ps[(tr * 4 + 1) * 64 + k];
            float a2 = Ps[(tr * 4 + 2) * 64 + k];
            float a3 = Ps[(tr * 4 + 3) * 64 + k];
            float4 b = *(const float4*)&Vs[k * 64 + tc * 4];
            o[0][0] += a0 * b.x; o[0][1] += a0 * b.y; o[0][2] += a0 * b.z; o[0][3] += a0 * b.w;
            o[1][0] += a1 * b.x; o[1][1] += a1 * b.y; o[1][2] += a1 * b.z; o[1][3] += a1 * b.w;
            o[2][0] += a2 * b.x; o[2][1] += a2 * b.y; o[2][2] += a2 * b.z; o[2][3] += a2 * b.w;
            o[3][0] += a3 * b.x; o[3][1] += a3 * b.y; o[3][2] += a3 * b.z; o[3][3] += a3 * b.w;
        }
    }

#pragma unroll
    for (int ii = 0; ii < 4; ii++) {
        const float inv = 1.f / lsum[ii];
        const int row = tr * 4 + ii;
        *(float4*)(Op + row * HDIM + tc * 4) =
            make_float4(o[ii][0] * inv, o[ii][1] * inv, o[ii][2] * inv, o[ii][3] * inv);
    }
}

// ---------------------------------------------------------------------------
extern "C" void kernel_launch(void* const* d_in, const int* in_sizes, int n_in,
                              void* d_out, int out_size)
{
    const float* X  = (const float*)d_in[0];
    const float* Wq = (const float*)d_in[1];
    const float* Wk = (const float*)d_in[2];
    const float* Wv = (const float*)d_in[3];
    const float* Wo = (const float*)d_in[4];
    const float* bo = (const float*)d_in[5];
    float* out = (float*)d_out;

    const int attn_smem = (2 * 64 * QS_STRIDE + 2 * 64 * 64) * (int)sizeof(float);
    cudaFuncSetAttribute(attn_kernel, cudaFuncAttributeMaxDynamicSharedMemorySize, attn_smem);
    cudaFuncSetAttribute(qkv_mma_kernel, cudaFuncAttributeMaxDynamicSharedMemorySize, GSMEM);
    cudaFuncSetAttribute(out_mma_kernel, cudaFuncAttributeMaxDynamicSharedMemorySize, GSMEM);

    qkv_mma_kernel<<<dim3(DMODEL / GBN, MROWS / GBM, 3), 256, GSMEM>>>(X, Wq, Wk, Wv);
    attn_kernel<<<dim3(SEQ / 64, BHCNT), 256, attn_smem>>>();
    out_mma_kernel<<<dim3(DMODEL / GBN, MROWS / GBM), 256, GSMEM>>>(Wo, bo, out);
}

// round 5
// speedup vs baseline: 2.5981x; 2.3053x over previous
#include <cuda_runtime.h>
#include <cuda_bf16.h>
#include <cstdint>

#define SEQ    2048
#define DMODEL 1024
#define HDIM   64
#define MROWS  4096
#define BHCNT  32
#define WPR    512   // packed bf16x2 words per dmodel row

// ---------------- device scratch (allocation-free rule) ----------------
__device__ uint32_t g_xhi[MROWS*WPR], g_xlo[MROWS*WPR];
__device__ uint32_t g_wqh[DMODEL*WPR], g_wql[DMODEL*WPR];
__device__ uint32_t g_wkh[DMODEL*WPR], g_wkl[DMODEL*WPR];
__device__ uint32_t g_wvh[DMODEL*WPR], g_wvl[DMODEL*WPR];
__device__ uint32_t g_woh[DMODEL*WPR], g_wol[DMODEL*WPR];
__device__ uint32_t g_qh [MROWS*WPR], g_ql [MROWS*WPR];
__device__ uint32_t g_kh [MROWS*WPR], g_kl [MROWS*WPR];
__device__ float    g_v  [MROWS*DMODEL];
__device__ uint32_t g_ah [MROWS*WPR], g_al [MROWS*WPR];

// ---------------- helpers ----------------
__device__ __forceinline__ uint32_t smem_u32(const void* p) {
    uint32_t a;
    asm("{ .reg .u64 t; cvta.to.shared.u64 t, %1; cvt.u32.u64 %0, t; }" : "=r"(a) : "l"(p));
    return a;
}
__device__ __forceinline__ void cp_async16(uint32_t s, const void* g) {
    asm volatile("cp.async.cg.shared.global [%0], [%1], 16;" ::"r"(s), "l"(g) : "memory");
}
#define CP_COMMIT() asm volatile("cp.async.commit_group;" ::: "memory")
#define CP_WAIT(n)  asm volatile("cp.async.wait_group %0;" ::"n"(n) : "memory")

// split f0,f1 (even,odd) into bf16 hi-word and lo(residual)-word; even in low half
__device__ __forceinline__ void split2(float f0, float f1, uint32_t& hw, uint32_t& lw) {
    __nv_bfloat16 h0 = __float2bfloat16(f0), h1 = __float2bfloat16(f1);
    float r0 = f0 - __bfloat162float(h0);
    float r1 = f1 - __bfloat162float(h1);
    __nv_bfloat16 e0 = __float2bfloat16(r0), e1 = __float2bfloat16(r1);
    hw = (uint32_t)__bfloat16_as_ushort(h0) | ((uint32_t)__bfloat16_as_ushort(h1) << 16);
    lw = (uint32_t)__bfloat16_as_ushort(e0) | ((uint32_t)__bfloat16_as_ushort(e1) << 16);
}
__device__ __forceinline__ void mma_bf16(float* c, const uint32_t* a, const uint32_t* b) {
    asm volatile(
        "mma.sync.aligned.m16n8k16.row.col.f32.bf16.bf16.f32 "
        "{%0,%1,%2,%3}, {%4,%5,%6,%7}, {%8,%9}, {%0,%1,%2,%3};"
        : "+f"(c[0]), "+f"(c[1]), "+f"(c[2]), "+f"(c[3])
        : "r"(a[0]), "r"(a[1]), "r"(a[2]), "r"(a[3]), "r"(b[0]), "r"(b[1]));
}

// ---------------- pre-split pass: fp32 -> packed bf16 hi/lo ----------------
__global__ void __launch_bounds__(256) split_all_kernel(const float* __restrict__ X,
                                                        const float* __restrict__ Wq,
                                                        const float* __restrict__ Wk,
                                                        const float* __restrict__ Wv,
                                                        const float* __restrict__ Wo)
{
    const int i = blockIdx.x * 256 + threadIdx.x;
    const int NX = MROWS * WPR;           // 2097152
    const int NW = DMODEL * WPR;          // 524288
    uint32_t h, l;
    if (i < NX) {
        float2 v = ((const float2*)X)[i];
        split2(v.x, v.y, h, l);
        g_xhi[i] = h; g_xlo[i] = l;
    } else {
        int t = i - NX;
        int sel = t >> 19, idx = t & (NW - 1);
        const float* src; uint32_t *dh, *dl;
        if      (sel == 0) { src = Wq; dh = g_wqh; dl = g_wql; }
        else if (sel == 1) { src = Wk; dh = g_wkh; dl = g_wkl; }
        else if (sel == 2) { src = Wv; dh = g_wvh; dl = g_wvl; }
        else               { src = Wo; dh = g_woh; dl = g_wol; }
        float2 v = ((const float2*)src)[idx];
        split2(v.x, v.y, h, l);
        dh[idx] = h; dl[idx] = l;
    }
}

// ---------------- bf16-split GEMM: C[M,N] = A @ W^T ----------------
// 128x128 tile, BK=64 (32 words), 3-stage cp.async, 256 threads (8 warps 2x4).
#define BKW 32
#define STGW (4 * 128 * BKW)        // words per stage (Ah,Al,Bh,Bl)
#define NSTG 3
#define GEMM_SMEM (NSTG * STGW * 4) // 192KB

// mode: 0 = write packed (OH/OL), 1 = write fp32 Cf, 2 = fp32 Cf + bias
__device__ __forceinline__ void gemm_body(const uint32_t* __restrict__ Ah,
                                          const uint32_t* __restrict__ Al,
                                          const uint32_t* __restrict__ Bh,
                                          const uint32_t* __restrict__ Bl,
                                          int mode,
                                          float* __restrict__ Cf,
                                          uint32_t* __restrict__ OH,
                                          uint32_t* __restrict__ OL,
                                          const float* __restrict__ bias)
{
    extern __shared__ uint32_t sm[];
    const uint32_t smu = smem_u32(sm);
    const int tid = threadIdx.x;
    const int wid = tid >> 5, lane = tid & 31;
    const int gr = lane >> 2, tg = lane & 3;
    const int m0 = blockIdx.y * 128, n0 = blockIdx.x * 128;
    const int wm = (wid >> 2) * 64, wn = (wid & 3) * 32;

    float acc[4][4][4];
#pragma unroll
    for (int i = 0; i < 4; i++)
#pragma unroll
        for (int j = 0; j < 4; j++)
#pragma unroll
            for (int c = 0; c < 4; c++) acc[i][j][c] = 0.f;

    auto load_stage = [&](int kt, int stg) {
        const uint32_t sb = smu + stg * STGW * 4;
#pragma unroll
        for (int it = 0; it < 16; it++) {
            const int c = tid + it * 256;
            const int part = c >> 10;
            const int r = (c >> 3) & 127;
            const int jj = c & 7;
            const uint32_t dst = sb + (part * 4096 + r * 32 + ((jj ^ (r & 7)) << 2)) * 4;
            const uint32_t* src;
            if      (part == 0) src = Ah + (size_t)(m0 + r) * WPR;
            else if (part == 1) src = Al + (size_t)(m0 + r) * WPR;
            else if (part == 2) src = Bh + (size_t)(n0 + r) * WPR;
            else                src = Bl + (size_t)(n0 + r) * WPR;
            cp_async16(dst, src + kt * BKW + jj * 4);
        }
    };

    load_stage(0, 0); CP_COMMIT();
    load_stage(1, 1); CP_COMMIT();

    for (int kt = 0; kt < 16; kt++) {
        const int stg = kt % NSTG;
        CP_WAIT(1);
        __syncthreads();
        const uint32_t* sAh = sm + stg * STGW;
        const uint32_t* sAl = sAh + 4096;
        const uint32_t* sBh = sAh + 8192;
        const uint32_t* sBl = sAh + 12288;
#pragma unroll
        for (int kc = 0; kc < 4; kc++) {
            uint32_t ah[4][4], al[4][4];
#pragma unroll
            for (int mi = 0; mi < 4; mi++) {
                const int r = wm + mi * 16 + gr;
                const int ch0 = ((2 * kc) ^ (r & 7)) << 2;
                const int ch1 = ((2 * kc + 1) ^ (r & 7)) << 2;
                ah[mi][0] = sAh[r * 32 + ch0 + tg];
                ah[mi][1] = sAh[(r + 8) * 32 + ch0 + tg];
                ah[mi][2] = sAh[r * 32 + ch1 + tg];
                ah[mi][3] = sAh[(r + 8) * 32 + ch1 + tg];
                al[mi][0] = sAl[r * 32 + ch0 + tg];
                al[mi][1] = sAl[(r + 8) * 32 + ch0 + tg];
                al[mi][2] = sAl[r * 32 + ch1 + tg];
                al[mi][3] = sAl[(r + 8) * 32 + ch1 + tg];
            }
#pragma unroll
            for (int nj = 0; nj < 4; nj++) {
                const int n = wn + nj * 8 + gr;
                const int ch0 = ((2 * kc) ^ (n & 7)) << 2;
                const int ch1 = ((2 * kc + 1) ^ (n & 7)) << 2;
                uint32_t bh_[2] = { sBh[n * 32 + ch0 + tg], sBh[n * 32 + ch1 + tg] };
                uint32_t bl_[2] = { sBl[n * 32 + ch0 + tg], sBl[n * 32 + ch1 + tg] };
#pragma unroll
                for (int mi = 0; mi < 4; mi++) {
                    mma_bf16(acc[mi][nj], ah[mi], bh_);
                    mma_bf16(acc[mi][nj], ah[mi], bl_);
                    mma_bf16(acc[mi][nj], al[mi], bh_);
                }
            }
        }
        __syncthreads();
        if (kt + 2 < 16) load_stage(kt + 2, (kt + 2) % NSTG);
        CP_COMMIT();
    }

    // epilogue
#pragma unroll
    for (int mi = 0; mi < 4; mi++) {
        const int r0 = m0 + wm + mi * 16 + gr;
#pragma unroll
        for (int nj = 0; nj < 4; nj++) {
            const int c0 = n0 + wn + nj * 8 + 2 * tg;
            float v0 = acc[mi][nj][0], v1 = acc[mi][nj][1];
            float v2 = acc[mi][nj][2], v3 = acc[mi][nj][3];
            if (mode == 0) {
                uint32_t h, l;
                split2(v0, v1, h, l);
                OH[(size_t)r0 * WPR + (c0 >> 1)] = h;
                OL[(size_t)r0 * WPR + (c0 >> 1)] = l;
                split2(v2, v3, h, l);
                OH[(size_t)(r0 + 8) * WPR + (c0 >> 1)] = h;
                OL[(size_t)(r0 + 8) * WPR + (c0 >> 1)] = l;
            } else {
                if (mode == 2) {
                    const float b0 = bias[c0], b1 = bias[c0 + 1];
                    v0 += b0; v1 += b1; v2 += b0; v3 += b1;
                }
                *(float2*)(Cf + (size_t)r0 * DMODEL + c0) = make_float2(v0, v1);
                *(float2*)(Cf + (size_t)(r0 + 8) * DMODEL + c0) = make_float2(v2, v3);
            }
        }
    }
}

__global__ void __launch_bounds__(256) qkv_kernel()
{
    const int z = blockIdx.z;
    if (z == 0)      gemm_body(g_xhi, g_xlo, g_wqh, g_wql, 0, nullptr, g_qh, g_ql, nullptr);
    else if (z == 1) gemm_body(g_xhi, g_xlo, g_wkh, g_wkl, 0, nullptr, g_kh, g_kl, nullptr);
    else             gemm_body(g_xhi, g_xlo, g_wvh, g_wvl, 1, g_v, nullptr, nullptr, nullptr);
}

__global__ void __launch_bounds__(256) out_kernel(const float* __restrict__ bias,
                                                  float* __restrict__ out)
{
    gemm_body(g_ah, g_al, g_woh, g_wol, 2, out, nullptr, nullptr, bias);
}

// ---------------- tensor-core causal flash attention ----------------
// CTA: 128 query rows x one bh. 8 warps x 16 rows. kv tiles of 64.
// smem (uint32 words): KH 0..2047 | KL 2048.. | VTH 4096.. | VTL 6144.. | VS(fp32) 8192..12287
// Q staging (prologue only): QH 4096..8191, QL 8192..12287
#define ATT_SMEM (12288 * 4)

__global__ void __launch_bounds__(256) attn_kernel()
{
    extern __shared__ uint32_t sm[];
    const uint32_t smu = smem_u32(sm);
    const int tid = threadIdx.x;
    const int wid = tid >> 5, lane = tid & 31;
    const int gr = lane >> 2, tg = lane & 3;
    const int qi = 15 - blockIdx.x;          // LPT-ish: big tiles first
    const int bh = blockIdx.y;
    const int qbase = qi * 128;
    const size_t wbase = (size_t)bh * 65536; // packed-word base of head slab

    // ---- stage Q (packed) and load fragments ----
#pragma unroll
    for (int it = 0; it < 4; it++) {
        const int i = tid + it * 256;
        const int r = i >> 3, j = i & 7;
        const uint32_t dst = (r * 32 + ((j ^ (r & 7)) << 2)) * 4;
        cp_async16(smu + (4096 * 4) + dst, g_qh + wbase + (size_t)(qbase + r) * 32 + j * 4);
        cp_async16(smu + (8192 * 4) + dst, g_ql + wbase + (size_t)(qbase + r) * 32 + j * 4);
    }
    CP_COMMIT(); CP_WAIT(0);
    __syncthreads();

    uint32_t qh[4][4], ql[4][4];
    {
        const int r = wid * 16 + gr;
#pragma unroll
        for (int kc = 0; kc < 4; kc++) {
            const int ch0 = ((2 * kc) ^ (r & 7)) << 2;
            const int ch1 = ((2 * kc + 1) ^ (r & 7)) << 2;
            qh[kc][0] = sm[4096 + r * 32 + ch0 + tg];
            qh[kc][1] = sm[4096 + (r + 8) * 32 + ch0 + tg];
            qh[kc][2] = sm[4096 + r * 32 + ch1 + tg];
            qh[kc][3] = sm[4096 + (r + 8) * 32 + ch1 + tg];
            ql[kc][0] = sm[8192 + r * 32 + ch0 + tg];
            ql[kc][1] = sm[8192 + (r + 8) * 32 + ch0 + tg];
            ql[kc][2] = sm[8192 + r * 32 + ch1 + tg];
            ql[kc][3] = sm[8192 + (r + 8) * 32 + ch1 + tg];
        }
    }
    __syncthreads();   // done with Q staging area

    float m0 = -1e30f, m1 = -1e30f, l0 = 0.f, l1 = 0.f;
    float oacc[8][4];
#pragma unroll
    for (int nf = 0; nf < 8; nf++)
#pragma unroll
        for (int c = 0; c < 4; c++) oacc[nf][c] = 0.f;

    const int numj = 2 * qi + 2;
    for (int j = 0; j < numj; j++) {
        const int kvb = j * 64;
        // ---- load K (packed hi/lo) and V (fp32) ----
#pragma unroll
        for (int it = 0; it < 8; it++) {
            const int i = tid + it * 256;
            if (i < 512) {
                const int r = i >> 3, c = i & 7;
                const uint32_t dst = (r * 32 + ((c ^ (r & 7)) << 2)) * 4;
                cp_async16(smu + dst, g_kh + wbase + (size_t)(kvb + r) * 32 + c * 4);
            } else if (i < 1024) {
                const int v = i - 512, r = v >> 3, c = v & 7;
                const uint32_t dst = (2048 + r * 32 + ((c ^ (r & 7)) << 2)) * 4;
                cp_async16(smu + dst, g_kl + wbase + (size_t)(kvb + r) * 32 + c * 4);
            } else {
                const int v = i - 1024, r = v >> 4, c = v & 15;
                cp_async16(smu + (8192 + r * 64 + c * 4) * 4,
                           g_v + (size_t)bh * 131072 + (size_t)(kvb + r) * 64 + c * 4);
            }
        }
        CP_COMMIT(); CP_WAIT(0);
        __syncthreads();

        // ---- transpose + split V into VTH/VTL [hd][kv-pair] ----
        {
            const int hd = tid >> 2;
            const int pb = (tid & 3) << 3;
            const float* vsf = (const float*)&sm[8192];
#pragma unroll
            for (int i2 = 0; i2 < 8; i2++) {
                const int p = pb + i2;
                const float f0 = vsf[(2 * p) * 64 + hd];
                const float f1 = vsf[(2 * p + 1) * 64 + hd];
                uint32_t hw, lw;
                split2(f0, f1, hw, lw);
                const int phys = hd * 32 + (((p >> 2) ^ (hd & 7)) << 2) + (p & 3);
                sm[4096 + phys] = hw;
                sm[6144 + phys] = lw;
            }
        }
        __syncthreads();

        // ---- S = Q K^T (bf16-split) ----
        float s[8][4];
#pragma unroll
        for (int nf = 0; nf < 8; nf++)
#pragma unroll
            for (int c = 0; c < 4; c++) s[nf][c] = 0.f;
#pragma unroll
        for (int kc = 0; kc < 4; kc++) {
#pragma unroll
            for (int nf = 0; nf < 8; nf++) {
                const int n = nf * 8 + gr;
                const int ch0 = ((2 * kc) ^ (n & 7)) << 2;
                const int ch1 = ((2 * kc + 1) ^ (n & 7)) << 2;
                uint32_t bh_[2] = { sm[n * 32 + ch0 + tg], sm[n * 32 + ch1 + tg] };
                uint32_t bl_[2] = { sm[2048 + n * 32 + ch0 + tg], sm[2048 + n * 32 + ch1 + tg] };
                mma_bf16(s[nf], qh[kc], bh_);
                mma_bf16(s[nf], qh[kc], bl_);
                mma_bf16(s[nf], ql[kc], bh_);
            }
        }

        // ---- causal mask (diagonal tiles only) ----
        if (j >= 2 * qi) {
            const int row0 = qbase + wid * 16 + gr, row1 = row0 + 8;
#pragma unroll
            for (int nf = 0; nf < 8; nf++) {
                const int col = kvb + nf * 8 + 2 * tg;
                if (col > row0)     s[nf][0] = -1e30f;
                if (col + 1 > row0) s[nf][1] = -1e30f;
                if (col > row1)     s[nf][2] = -1e30f;
                if (col + 1 > row1) s[nf][3] = -1e30f;
            }
        }

        // ---- online softmax ----
        float rm0 = -1e30f, rm1 = -1e30f;
#pragma unroll
        for (int nf = 0; nf < 8; nf++) {
            rm0 = fmaxf(rm0, fmaxf(s[nf][0], s[nf][1]));
            rm1 = fmaxf(rm1, fmaxf(s[nf][2], s[nf][3]));
        }
        rm0 = fmaxf(rm0, __shfl_xor_sync(0xffffffffu, rm0, 1));
        rm0 = fmaxf(rm0, __shfl_xor_sync(0xffffffffu, rm0, 2));
        rm1 = fmaxf(rm1, __shfl_xor_sync(0xffffffffu, rm1, 1));
        rm1 = fmaxf(rm1, __shfl_xor_sync(0xffffffffu, rm1, 2));
        const float mn0 = fmaxf(m0, rm0), mn1 = fmaxf(m1, rm1);
        const float sc0 = __expf(m0 - mn0), sc1 = __expf(m1 - mn1);
        m0 = mn0; m1 = mn1;
        float rs0 = 0.f, rs1 = 0.f;
#pragma unroll
        for (int nf = 0; nf < 8; nf++) {
            s[nf][0] = __expf(s[nf][0] - mn0);
            s[nf][1] = __expf(s[nf][1] - mn0);
            s[nf][2] = __expf(s[nf][2] - mn1);
            s[nf][3] = __expf(s[nf][3] - mn1);
            rs0 += s[nf][0] + s[nf][1];
            rs1 += s[nf][2] + s[nf][3];
        }
        rs0 += __shfl_xor_sync(0xffffffffu, rs0, 1);
        rs0 += __shfl_xor_sync(0xffffffffu, rs0, 2);
        rs1 += __shfl_xor_sync(0xffffffffu, rs1, 1);
        rs1 += __shfl_xor_sync(0xffffffffu, rs1, 2);
        l0 = l0 * sc0 + rs0;
        l1 = l1 * sc1 + rs1;
#pragma unroll
        for (int nf = 0; nf < 8; nf++) {
            oacc[nf][0] *= sc0; oacc[nf][1] *= sc0;
            oacc[nf][2] *= sc1; oacc[nf][3] *= sc1;
        }

        // ---- O += P V (P packed in-register) ----
#pragma unroll
        for (int kc = 0; kc < 4; kc++) {
            uint32_t pah[4], pal[4];
            split2(s[2 * kc][0],     s[2 * kc][1],     pah[0], pal[0]);
            split2(s[2 * kc][2],     s[2 * kc][3],     pah[1], pal[1]);
            split2(s[2 * kc + 1][0], s[2 * kc + 1][1], pah[2], pal[2]);
            split2(s[2 * kc + 1][2], s[2 * kc + 1][3], pah[3], pal[3]);
#pragma unroll
            for (int nf = 0; nf < 8; nf++) {
                const int n = nf * 8 + gr;
                const int ch0 = ((2 * kc) ^ (n & 7)) << 2;
                const int ch1 = ((2 * kc + 1) ^ (n & 7)) << 2;
                uint32_t vbh[2] = { sm[4096 + n * 32 + ch0 + tg], sm[4096 + n * 32 + ch1 + tg] };
                uint32_t vbl[2] = { sm[6144 + n * 32 + ch0 + tg], sm[6144 + n * 32 + ch1 + tg] };
                mma_bf16(oacc[nf], pah, vbh);
                mma_bf16(oacc[nf], pah, vbl);
                mma_bf16(oacc[nf], pal, vbh);
            }
        }
        __syncthreads();   // all warps done reading before next tile's loads
    }

    // ---- finalize: O /= l, write packed for out-GEMM ----
    const float inv0 = 1.f / l0, inv1 = 1.f / l1;
    const int row0 = qbase + wid * 16 + gr;
#pragma unroll
    for (int nf = 0; nf < 8; nf++) {
        uint32_t h, l;
        split2(oacc[nf][0] * inv0, oacc[nf][1] * inv0, h, l);
        const int w = nf * 4 + tg;
        g_ah[wbase + (size_t)row0 * 32 + w] = h;
        g_al[wbase + (size_t)row0 * 32 + w] = l;
        split2(oacc[nf][2] * inv1, oacc[nf][3] * inv1, h, l);
        g_ah[wbase + (size_t)(row0 + 8) * 32 + w] = h;
        g_al[wbase + (size_t)(row0 + 8) * 32 + w] = l;
    }
}

// ---------------------------------------------------------------------------
extern "C" void kernel_launch(void* const* d_in, const int* in_sizes, int n_in,
                              void* d_out, int out_size)
{
    const float* X  = (const float*)d_in[0];
    const float* Wq = (const float*)d_in[1];
    const float* Wk = (const float*)d_in[2];
    const float* Wv = (const float*)d_in[3];
    const float* Wo = (const float*)d_in[4];
    const float* bo = (const float*)d_in[5];
    float* out = (float*)d_out;

    cudaFuncSetAttribute(qkv_kernel, cudaFuncAttributeMaxDynamicSharedMemorySize, GEMM_SMEM);
    cudaFuncSetAttribute(out_kernel, cudaFuncAttributeMaxDynamicSharedMemorySize, GEMM_SMEM);
    cudaFuncSetAttribute(attn_kernel, cudaFuncAttributeMaxDynamicSharedMemorySize, ATT_SMEM);

    // 1) split inputs/weights into bf16 hi/lo packed
    const int total_words = MROWS * WPR + 4 * DMODEL * WPR;  // 4194304
    split_all_kernel<<<total_words / 256, 256>>>(X, Wq, Wk, Wv, Wo);
    // 2) Q,K (packed) + V (fp32) projections
    qkv_kernel<<<dim3(DMODEL / 128, MROWS / 128, 3), 256, GEMM_SMEM>>>();
    // 3) causal attention (tensor cores), writes packed attention output
    attn_kernel<<<dim3(16, BHCNT), 256, ATT_SMEM>>>();
    // 4) output projection + bias
    out_kernel<<<dim3(DMODEL / 128, MROWS / 128), 256, GEMM_SMEM>>>(bo, out);
}

// round 6
// speedup vs baseline: 2.6066x; 1.0033x over previous
#include <cuda_runtime.h>
#include <cuda_bf16.h>
#include <cstdint>

#define SEQ    2048
#define DMODEL 1024
#define HDIM   64
#define MROWS  4096
#define BHCNT  32
#define WPR    512   // packed bf16x2 words per dmodel row

// ---------------- device scratch (allocation-free rule) ----------------
__device__ uint32_t g_xhi[MROWS*WPR], g_xlo[MROWS*WPR];
__device__ uint32_t g_wqh[DMODEL*WPR], g_wql[DMODEL*WPR];
__device__ uint32_t g_wkh[DMODEL*WPR], g_wkl[DMODEL*WPR];
__device__ uint32_t g_wvh[DMODEL*WPR], g_wvl[DMODEL*WPR];
__device__ uint32_t g_woh[DMODEL*WPR], g_wol[DMODEL*WPR];
__device__ uint32_t g_qh [MROWS*WPR], g_ql [MROWS*WPR];
__device__ uint32_t g_kh [MROWS*WPR], g_kl [MROWS*WPR];
__device__ float    g_v  [MROWS*DMODEL];
// V transposed+split, attention-B-operand-ready: [bh][kvtile 32][hd 64][word 32]
__device__ uint32_t g_vth[BHCNT*32*64*32], g_vtl[BHCNT*32*64*32];
__device__ uint32_t g_ah [MROWS*WPR], g_al [MROWS*WPR];

// ---------------- helpers ----------------
__device__ __forceinline__ uint32_t smem_u32(const void* p) {
    uint32_t a;
    asm("{ .reg .u64 t; cvta.to.shared.u64 t, %1; cvt.u32.u64 %0, t; }" : "=r"(a) : "l"(p));
    return a;
}
__device__ __forceinline__ void cp_async16(uint32_t s, const void* g) {
    asm volatile("cp.async.cg.shared.global [%0], [%1], 16;" ::"r"(s), "l"(g) : "memory");
}
#define CP_COMMIT() asm volatile("cp.async.commit_group;" ::: "memory")
#define CP_WAIT(n)  asm volatile("cp.async.wait_group %0;" ::"n"(n) : "memory")

__device__ __forceinline__ void split2(float f0, float f1, uint32_t& hw, uint32_t& lw) {
    __nv_bfloat16 h0 = __float2bfloat16(f0), h1 = __float2bfloat16(f1);
    float r0 = f0 - __bfloat162float(h0);
    float r1 = f1 - __bfloat162float(h1);
    __nv_bfloat16 e0 = __float2bfloat16(r0), e1 = __float2bfloat16(r1);
    hw = (uint32_t)__bfloat16_as_ushort(h0) | ((uint32_t)__bfloat16_as_ushort(h1) << 16);
    lw = (uint32_t)__bfloat16_as_ushort(e0) | ((uint32_t)__bfloat16_as_ushort(e1) << 16);
}
__device__ __forceinline__ void mma_bf16(float* c, const uint32_t* a, const uint32_t* b) {
    asm volatile(
        "mma.sync.aligned.m16n8k16.row.col.f32.bf16.bf16.f32 "
        "{%0,%1,%2,%3}, {%4,%5,%6,%7}, {%8,%9}, {%0,%1,%2,%3};"
        : "+f"(c[0]), "+f"(c[1]), "+f"(c[2]), "+f"(c[3])
        : "r"(a[0]), "r"(a[1]), "r"(a[2]), "r"(a[3]), "r"(b[0]), "r"(b[1]));
}

// ---------------- pre-split pass: fp32 -> packed bf16 hi/lo ----------------
__global__ void __launch_bounds__(256) split_all_kernel(const float* __restrict__ X,
                                                        const float* __restrict__ Wq,
                                                        const float* __restrict__ Wk,
                                                        const float* __restrict__ Wv,
                                                        const float* __restrict__ Wo)
{
    const int i = blockIdx.x * 256 + threadIdx.x;
    const int NX = MROWS * WPR;
    const int NW = DMODEL * WPR;
    uint32_t h, l;
    if (i < NX) {
        float2 v = ((const float2*)X)[i];
        split2(v.x, v.y, h, l);
        g_xhi[i] = h; g_xlo[i] = l;
    } else {
        int t = i - NX;
        int sel = t >> 19, idx = t & (NW - 1);
        const float* src; uint32_t *dh, *dl;
        if      (sel == 0) { src = Wq; dh = g_wqh; dl = g_wql; }
        else if (sel == 1) { src = Wk; dh = g_wkh; dl = g_wkl; }
        else if (sel == 2) { src = Wv; dh = g_wvh; dl = g_wvl; }
        else               { src = Wo; dh = g_woh; dl = g_wol; }
        float2 v = ((const float2*)src)[idx];
        split2(v.x, v.y, h, l);
        dh[idx] = h; dl[idx] = l;
    }
}

// ---------------- V transpose+split pre-pass ----------------
// One CTA per (kvtile, bh): reads g_v[bh][j*64..+64][64] fp32,
// writes g_vth/g_vtl[bh][j][hd][word] (word = kv-pair, even kv in low half).
__global__ void __launch_bounds__(256) vtrans_kernel()
{
    __shared__ float vs[64 * 65];
    const int j = blockIdx.x, bh = blockIdx.y;
    const int tid = threadIdx.x;
    const float* src = g_v + (size_t)bh * (SEQ * HDIM) + (size_t)j * 64 * HDIM;
#pragma unroll
    for (int it = 0; it < 16; it++) {
        const int i = tid + it * 256;
        const int kv = i >> 6, hd = i & 63;
        vs[kv * 65 + hd] = src[kv * 64 + hd];
    }
    __syncthreads();
    const size_t obase = ((size_t)bh * 32 + j) * 2048;
#pragma unroll
    for (int it = 0; it < 8; it++) {
        const int i = tid + it * 256;
        const int hd = i >> 5, w = i & 31;
        uint32_t h, l;
        split2(vs[(2 * w) * 65 + hd], vs[(2 * w + 1) * 65 + hd], h, l);
        g_vth[obase + hd * 32 + w] = h;
        g_vtl[obase + hd * 32 + w] = l;
    }
}

// ---------------- bf16-split GEMM (unchanged from R5) ----------------
#define BKW 32
#define STGW (4 * 128 * BKW)
#define NSTG 3
#define GEMM_SMEM (NSTG * STGW * 4)

__device__ __forceinline__ void gemm_body(const uint32_t* __restrict__ Ah,
                                          const uint32_t* __restrict__ Al,
                                          const uint32_t* __restrict__ Bh,
                                          const uint32_t* __restrict__ Bl,
                                          int mode,
                                          float* __restrict__ Cf,
                                          uint32_t* __restrict__ OH,
                                          uint32_t* __restrict__ OL,
                                          const float* __restrict__ bias)
{
    extern __shared__ uint32_t sm[];
    const uint32_t smu = smem_u32(sm);
    const int tid = threadIdx.x;
    const int wid = tid >> 5, lane = tid & 31;
    const int gr = lane >> 2, tg = lane & 3;
    const int m0 = blockIdx.y * 128, n0 = blockIdx.x * 128;
    const int wm = (wid >> 2) * 64, wn = (wid & 3) * 32;

    float acc[4][4][4];
#pragma unroll
    for (int i = 0; i < 4; i++)
#pragma unroll
        for (int j = 0; j < 4; j++)
#pragma unroll
            for (int c = 0; c < 4; c++) acc[i][j][c] = 0.f;

    auto load_stage = [&](int kt, int stg) {
        const uint32_t sb = smu + stg * STGW * 4;
#pragma unroll
        for (int it = 0; it < 16; it++) {
            const int c = tid + it * 256;
            const int part = c >> 10;
            const int r = (c >> 3) & 127;
            const int jj = c & 7;
            const uint32_t dst = sb + (part * 4096 + r * 32 + ((jj ^ (r & 7)) << 2)) * 4;
            const uint32_t* src;
            if      (part == 0) src = Ah + (size_t)(m0 + r) * WPR;
            else if (part == 1) src = Al + (size_t)(m0 + r) * WPR;
            else if (part == 2) src = Bh + (size_t)(n0 + r) * WPR;
            else                src = Bl + (size_t)(n0 + r) * WPR;
            cp_async16(dst, src + kt * BKW + jj * 4);
        }
    };

    load_stage(0, 0); CP_COMMIT();
    load_stage(1, 1); CP_COMMIT();

    for (int kt = 0; kt < 16; kt++) {
        const int stg = kt % NSTG;
        CP_WAIT(1);
        __syncthreads();
        const uint32_t* sAh = sm + stg * STGW;
        const uint32_t* sAl = sAh + 4096;
        const uint32_t* sBh = sAh + 8192;
        const uint32_t* sBl = sAh + 12288;
#pragma unroll
        for (int kc = 0; kc < 4; kc++) {
            uint32_t ah[4][4], al[4][4];
#pragma unroll
            for (int mi = 0; mi < 4; mi++) {
                const int r = wm + mi * 16 + gr;
                const int ch0 = ((2 * kc) ^ (r & 7)) << 2;
                const int ch1 = ((2 * kc + 1) ^ (r & 7)) << 2;
                ah[mi][0] = sAh[r * 32 + ch0 + tg];
                ah[mi][1] = sAh[(r + 8) * 32 + ch0 + tg];
                ah[mi][2] = sAh[r * 32 + ch1 + tg];
                ah[mi][3] = sAh[(r + 8) * 32 + ch1 + tg];
                al[mi][0] = sAl[r * 32 + ch0 + tg];
                al[mi][1] = sAl[(r + 8) * 32 + ch0 + tg];
                al[mi][2] = sAl[r * 32 + ch1 + tg];
                al[mi][3] = sAl[(r + 8) * 32 + ch1 + tg];
            }
#pragma unroll
            for (int nj = 0; nj < 4; nj++) {
                const int n = wn + nj * 8 + gr;
                const int ch0 = ((2 * kc) ^ (n & 7)) << 2;
                const int ch1 = ((2 * kc + 1) ^ (n & 7)) << 2;
                uint32_t bh_[2] = { sBh[n * 32 + ch0 + tg], sBh[n * 32 + ch1 + tg] };
                uint32_t bl_[2] = { sBl[n * 32 + ch0 + tg], sBl[n * 32 + ch1 + tg] };
#pragma unroll
                for (int mi = 0; mi < 4; mi++) {
                    mma_bf16(acc[mi][nj], ah[mi], bh_);
                    mma_bf16(acc[mi][nj], ah[mi], bl_);
                    mma_bf16(acc[mi][nj], al[mi], bh_);
                }
            }
        }
        __syncthreads();
        if (kt + 2 < 16) load_stage(kt + 2, (kt + 2) % NSTG);
        CP_COMMIT();
    }

#pragma unroll
    for (int mi = 0; mi < 4; mi++) {
        const int r0 = m0 + wm + mi * 16 + gr;
#pragma unroll
        for (int nj = 0; nj < 4; nj++) {
            const int c0 = n0 + wn + nj * 8 + 2 * tg;
            float v0 = acc[mi][nj][0], v1 = acc[mi][nj][1];
            float v2 = acc[mi][nj][2], v3 = acc[mi][nj][3];
            if (mode == 0) {
                uint32_t h, l;
                split2(v0, v1, h, l);
                OH[(size_t)r0 * WPR + (c0 >> 1)] = h;
                OL[(size_t)r0 * WPR + (c0 >> 1)] = l;
                split2(v2, v3, h, l);
                OH[(size_t)(r0 + 8) * WPR + (c0 >> 1)] = h;
                OL[(size_t)(r0 + 8) * WPR + (c0 >> 1)] = l;
            } else {
                if (mode == 2) {
                    const float b0 = bias[c0], b1 = bias[c0 + 1];
                    v0 += b0; v1 += b1; v2 += b0; v3 += b1;
                }
                *(float2*)(Cf + (size_t)r0 * DMODEL + c0) = make_float2(v0, v1);
                *(float2*)(Cf + (size_t)(r0 + 8) * DMODEL + c0) = make_float2(v2, v3);
            }
        }
    }
}

__global__ void __launch_bounds__(256) qkv_kernel()
{
    const int z = blockIdx.z;
    if (z == 0)      gemm_body(g_xhi, g_xlo, g_wqh, g_wql, 0, nullptr, g_qh, g_ql, nullptr);
    else if (z == 1) gemm_body(g_xhi, g_xlo, g_wkh, g_wkl, 0, nullptr, g_kh, g_kl, nullptr);
    else             gemm_body(g_xhi, g_xlo, g_wvh, g_wvl, 1, g_v, nullptr, nullptr, nullptr);
}

__global__ void __launch_bounds__(256) out_kernel(const float* __restrict__ bias,
                                                  float* __restrict__ out)
{
    gemm_body(g_ah, g_al, g_woh, g_wol, 2, out, nullptr, nullptr, bias);
}

// ---------------- tensor-core causal flash attention ----------------
// CTA: 128 query rows x one bh. 8 warps x 16 rows. kv tiles of 64.
// Double-buffered stages (8192 words each): KH | KL | VTH | VTL (2048 apiece).
// Q prologue staged in stage0+stage1 area (8192 words) before pipeline start.
#define ATT_SMEM (16384 * 4)

__global__ void __launch_bounds__(256) attn_kernel()
{
    extern __shared__ uint32_t sm[];
    const uint32_t smu = smem_u32(sm);
    const int tid = threadIdx.x;
    const int wid = tid >> 5, lane = tid & 31;
    const int gr = lane >> 2, tg = lane & 3;
    const int qi = 15 - blockIdx.x;
    const int bh = blockIdx.y;
    const int qbase = qi * 128;
    const size_t wbase = (size_t)bh * 65536;        // packed-word base of head slab
    const size_t vtbase = (size_t)bh * 65536;       // g_vth tile base (32*2048)

    // ---- stage Q packed (QH words 0..4095, QL 4096..8191) ----
#pragma unroll
    for (int it = 0; it < 4; it++) {
        const int i = tid + it * 256;
        const int r = i >> 3, j = i & 7;
        const uint32_t dst = (r * 32 + ((j ^ (r & 7)) << 2)) * 4;
        cp_async16(smu + dst, g_qh + wbase + (size_t)(qbase + r) * 32 + j * 4);
        cp_async16(smu + (4096 * 4) + dst, g_ql + wbase + (size_t)(qbase + r) * 32 + j * 4);
    }
    CP_COMMIT(); CP_WAIT(0);
    __syncthreads();

    uint32_t qh[4][4], ql[4][4];
    {
        const int r = wid * 16 + gr;
#pragma unroll
        for (int kc = 0; kc < 4; kc++) {
            const int ch0 = ((2 * kc) ^ (r & 7)) << 2;
            const int ch1 = ((2 * kc + 1) ^ (r & 7)) << 2;
            qh[kc][0] = sm[r * 32 + ch0 + tg];
            qh[kc][1] = sm[(r + 8) * 32 + ch0 + tg];
            qh[kc][2] = sm[r * 32 + ch1 + tg];
            qh[kc][3] = sm[(r + 8) * 32 + ch1 + tg];
            ql[kc][0] = sm[4096 + r * 32 + ch0 + tg];
            ql[kc][1] = sm[4096 + (r + 8) * 32 + ch0 + tg];
            ql[kc][2] = sm[4096 + r * 32 + ch1 + tg];
            ql[kc][3] = sm[4096 + (r + 8) * 32 + ch1 + tg];
        }
    }
    __syncthreads();

    float m0 = -1e30f, m1 = -1e30f, l0 = 0.f, l1 = 0.f;
    float oacc[8][4];
#pragma unroll
    for (int nf = 0; nf < 8; nf++)
#pragma unroll
        for (int c = 0; c < 4; c++) oacc[nf][c] = 0.f;

    const int numj = 2 * qi + 2;

    // load K(hi/lo) + VT(hi/lo) for tile j into stage st
    auto load_kv = [&](int j, int st) {
        const uint32_t sb = smu + st * 8192 * 4;
#pragma unroll
        for (int it = 0; it < 8; it++) {
            const int c = tid + it * 256;
            const int part = c >> 9;
            const int r = (c >> 3) & 63;
            const int jj = c & 7;
            const uint32_t dst = sb + (part * 2048 + r * 32 + ((jj ^ (r & 7)) << 2)) * 4;
            const uint32_t* src;
            if      (part == 0) src = g_kh + wbase + (size_t)(j * 64 + r) * 32;
            else if (part == 1) src = g_kl + wbase + (size_t)(j * 64 + r) * 32;
            else if (part == 2) src = g_vth + vtbase + (size_t)j * 2048 + r * 32;
            else                src = g_vtl + vtbase + (size_t)j * 2048 + r * 32;
            cp_async16(dst, src + jj * 4);
        }
    };

    load_kv(0, 0); CP_COMMIT();

    for (int j = 0; j < numj; j++) {
        if (j + 1 < numj) load_kv(j + 1, (j + 1) & 1);
        CP_COMMIT();
        CP_WAIT(1);
        __syncthreads();

        const uint32_t* sb = sm + (j & 1) * 8192;   // KH | KL+2048 | VTH+4096 | VTL+6144
        const int kvb = j * 64;

        // ---- S = Q K^T (bf16-split) ----
        float s[8][4];
#pragma unroll
        for (int nf = 0; nf < 8; nf++)
#pragma unroll
            for (int c = 0; c < 4; c++) s[nf][c] = 0.f;
#pragma unroll
        for (int kc = 0; kc < 4; kc++) {
#pragma unroll
            for (int nf = 0; nf < 8; nf++) {
                const int n = nf * 8 + gr;
                const int ch0 = ((2 * kc) ^ (n & 7)) << 2;
                const int ch1 = ((2 * kc + 1) ^ (n & 7)) << 2;
                uint32_t bh_[2] = { sb[n * 32 + ch0 + tg], sb[n * 32 + ch1 + tg] };
                uint32_t bl_[2] = { sb[2048 + n * 32 + ch0 + tg], sb[2048 + n * 32 + ch1 + tg] };
                mma_bf16(s[nf], qh[kc], bh_);
                mma_bf16(s[nf], qh[kc], bl_);
                mma_bf16(s[nf], ql[kc], bh_);
            }
        }

        // ---- causal mask (diagonal tiles only) ----
        if (j >= 2 * qi) {
            const int row0 = qbase + wid * 16 + gr, row1 = row0 + 8;
#pragma unroll
            for (int nf = 0; nf < 8; nf++) {
                const int col = kvb + nf * 8 + 2 * tg;
                if (col > row0)     s[nf][0] = -1e30f;
                if (col + 1 > row0) s[nf][1] = -1e30f;
                if (col > row1)     s[nf][2] = -1e30f;
                if (col + 1 > row1) s[nf][3] = -1e30f;
            }
        }

        // ---- online softmax ----
        float rm0 = -1e30f, rm1 = -1e30f;
#pragma unroll
        for (int nf = 0; nf < 8; nf++) {
            rm0 = fmaxf(rm0, fmaxf(s[nf][0], s[nf][1]));
            rm1 = fmaxf(rm1, fmaxf(s[nf][2], s[nf][3]));
        }
        rm0 = fmaxf(rm0, __shfl_xor_sync(0xffffffffu, rm0, 1));
        rm0 = fmaxf(rm0, __shfl_xor_sync(0xffffffffu, rm0, 2));
        rm1 = fmaxf(rm1, __shfl_xor_sync(0xffffffffu, rm1, 1));
        rm1 = fmaxf(rm1, __shfl_xor_sync(0xffffffffu, rm1, 2));
        const float mn0 = fmaxf(m0, rm0), mn1 = fmaxf(m1, rm1);
        const float sc0 = __expf(m0 - mn0), sc1 = __expf(m1 - mn1);
        m0 = mn0; m1 = mn1;
        float rs0 = 0.f, rs1 = 0.f;
#pragma unroll
        for (int nf = 0; nf < 8; nf++) {
            s[nf][0] = __expf(s[nf][0] - mn0);
            s[nf][1] = __expf(s[nf][1] - mn0);
            s[nf][2] = __expf(s[nf][2] - mn1);
            s[nf][3] = __expf(s[nf][3] - mn1);
            rs0 += s[nf][0] + s[nf][1];
            rs1 += s[nf][2] + s[nf][3];
        }
        rs0 += __shfl_xor_sync(0xffffffffu, rs0, 1);
        rs0 += __shfl_xor_sync(0xffffffffu, rs0, 2);
        rs1 += __shfl_xor_sync(0xffffffffu, rs1, 1);
        rs1 += __shfl_xor_sync(0xffffffffu, rs1, 2);
        l0 = l0 * sc0 + rs0;
        l1 = l1 * sc1 + rs1;
#pragma unroll
        for (int nf = 0; nf < 8; nf++) {
            oacc[nf][0] *= sc0; oacc[nf][1] *= sc0;
            oacc[nf][2] *= sc1; oacc[nf][3] *= sc1;
        }

        // ---- O += P V (P split in-register; V pre-transposed/split) ----
#pragma unroll
        for (int kc = 0; kc < 4; kc++) {
            uint32_t pah[4], pal[4];
            split2(s[2 * kc][0],     s[2 * kc][1],     pah[0], pal[0]);
            split2(s[2 * kc][2],     s[2 * kc][3],     pah[1], pal[1]);
            split2(s[2 * kc + 1][0], s[2 * kc + 1][1], pah[2], pal[2]);
            split2(s[2 * kc + 1][2], s[2 * kc + 1][3], pah[3], pal[3]);
#pragma unroll
            for (int nf = 0; nf < 8; nf++) {
                const int n = nf * 8 + gr;
                const int ch0 = ((2 * kc) ^ (n & 7)) << 2;
                const int ch1 = ((2 * kc + 1) ^ (n & 7)) << 2;
                uint32_t vbh[2] = { sb[4096 + n * 32 + ch0 + tg], sb[4096 + n * 32 + ch1 + tg] };
                uint32_t vbl[2] = { sb[6144 + n * 32 + ch0 + tg], sb[6144 + n * 32 + ch1 + tg] };
                mma_bf16(oacc[nf], pah, vbh);
                mma_bf16(oacc[nf], pah, vbl);
                mma_bf16(oacc[nf], pal, vbh);
            }
        }
        __syncthreads();
    }

    // ---- finalize: O /= l, write packed for out-GEMM ----
    const float inv0 = 1.f / l0, inv1 = 1.f / l1;
    const int row0 = qbase + wid * 16 + gr;
#pragma unroll
    for (int nf = 0; nf < 8; nf++) {
        uint32_t h, l;
        split2(oacc[nf][0] * inv0, oacc[nf][1] * inv0, h, l);
        const int w = nf * 4 + tg;
        g_ah[wbase + (size_t)row0 * 32 + w] = h;
        g_al[wbase + (size_t)row0 * 32 + w] = l;
        split2(oacc[nf][2] * inv1, oacc[nf][3] * inv1, h, l);
        g_ah[wbase + (size_t)(row0 + 8) * 32 + w] = h;
        g_al[wbase + (size_t)(row0 + 8) * 32 + w] = l;
    }
}

// ---------------------------------------------------------------------------
extern "C" void kernel_launch(void* const* d_in, const int* in_sizes, int n_in,
                              void* d_out, int out_size)
{
    const float* X  = (const float*)d_in[0];
    const float* Wq = (const float*)d_in[1];
    const float* Wk = (const float*)d_in[2];
    const float* Wv = (const float*)d_in[3];
    const float* Wo = (const float*)d_in[4];
    const float* bo = (const float*)d_in[5];
    float* out = (float*)d_out;

    cudaFuncSetAttribute(qkv_kernel, cudaFuncAttributeMaxDynamicSharedMemorySize, GEMM_SMEM);
    cudaFuncSetAttribute(out_kernel, cudaFuncAttributeMaxDynamicSharedMemorySize, GEMM_SMEM);
    cudaFuncSetAttribute(attn_kernel, cudaFuncAttributeMaxDynamicSharedMemorySize, ATT_SMEM);

    const int total_words = MROWS * WPR + 4 * DMODEL * WPR;
    split_all_kernel<<<total_words / 256, 256>>>(X, Wq, Wk, Wv, Wo);
    qkv_kernel<<<dim3(DMODEL / 128, MROWS / 128, 3), 256, GEMM_SMEM>>>();
    vtrans_kernel<<<dim3(32, BHCNT), 256>>>();
    attn_kernel<<<dim3(16, BHCNT), 256, ATT_SMEM>>>();
    out_kernel<<<dim3(DMODEL / 128, MROWS / 128), 256, GEMM_SMEM>>>(bo, out);
}